// round 1
// baseline (speedup 1.0000x reference)
#include <cuda_runtime.h>
#include <math.h>
#include <float.h>

// Problem constants (fixed by the reference setup)
namespace {
constexpr int B_  = 2;
constexpr int S_  = 2048;
constexpr int D_  = 1024;
constexpr int H_  = 16;
constexpr int DH_ = 64;
constexpr int M_  = B_ * S_;          // 4096 rows (b,s)
}

// Scratch (device globals — no allocation allowed)
__device__ float g_qkv[(size_t)M_ * 3 * D_];           // [B,S,3,H,DH] flattened
__device__ float g_q[(size_t)B_ * H_ * S_ * DH_];      // [B,H,S,DH]
__device__ float g_k[(size_t)B_ * H_ * S_ * DH_];
__device__ float g_v[(size_t)B_ * H_ * S_ * DH_];
__device__ float g_attn[(size_t)M_ * D_];              // [B,S,D] (already head-merged)

// ---------------------------------------------------------------------------
// C[M,N] = A[M,K] * W[N,K]^T   (A row-major, W row-major "weights" layout)
// 64x64 tile, BK=16, 128 threads, each thread an 8x4 fragment.
// ---------------------------------------------------------------------------
__global__ __launch_bounds__(128)
void gemm_nt_kernel(const float* __restrict__ A, const float* __restrict__ W,
                    float* __restrict__ C, int M, int N, int K)
{
    constexpr int BM = 64, BN = 64, BK = 16;
    __shared__ float As[BK][BM + 4];
    __shared__ float Bs[BK][BN + 4];

    const int tid = threadIdx.x;
    const int bm  = blockIdx.y * BM;
    const int bn  = blockIdx.x * BN;
    const int ty  = tid >> 4;   // 0..7  -> 8 rows each
    const int tx  = tid & 15;   // 0..15 -> 4 cols each

    float acc[8][4];
#pragma unroll
    for (int i = 0; i < 8; i++)
#pragma unroll
        for (int j = 0; j < 4; j++) acc[i][j] = 0.f;

    for (int k0 = 0; k0 < K; k0 += BK) {
        // Load A tile (64 rows x 16 cols) transposed into As[k][m]
#pragma unroll
        for (int i = tid; i < BM * (BK / 4); i += 128) {
            int r = i >> 2, q = (i & 3) * 4;
            float4 v = *reinterpret_cast<const float4*>(A + (size_t)(bm + r) * K + k0 + q);
            As[q + 0][r] = v.x; As[q + 1][r] = v.y; As[q + 2][r] = v.z; As[q + 3][r] = v.w;
        }
#pragma unroll
        for (int i = tid; i < BN * (BK / 4); i += 128) {
            int r = i >> 2, q = (i & 3) * 4;
            float4 v = *reinterpret_cast<const float4*>(W + (size_t)(bn + r) * K + k0 + q);
            Bs[q + 0][r] = v.x; Bs[q + 1][r] = v.y; Bs[q + 2][r] = v.z; Bs[q + 3][r] = v.w;
        }
        __syncthreads();

#pragma unroll
        for (int k = 0; k < BK; k++) {
            float4 a0 = *reinterpret_cast<const float4*>(&As[k][ty * 8]);
            float4 a1 = *reinterpret_cast<const float4*>(&As[k][ty * 8 + 4]);
            float4 bb = *reinterpret_cast<const float4*>(&Bs[k][tx * 4]);
            float av[8] = {a0.x, a0.y, a0.z, a0.w, a1.x, a1.y, a1.z, a1.w};
            float bv[4] = {bb.x, bb.y, bb.z, bb.w};
#pragma unroll
            for (int i = 0; i < 8; i++)
#pragma unroll
                for (int j = 0; j < 4; j++)
                    acc[i][j] += av[i] * bv[j];
        }
        __syncthreads();
    }

#pragma unroll
    for (int i = 0; i < 8; i++) {
        float4 o = make_float4(acc[i][0], acc[i][1], acc[i][2], acc[i][3]);
        *reinterpret_cast<float4*>(C + (size_t)(bm + ty * 8 + i) * N + bn + tx * 4) = o;
    }
}

// ---------------------------------------------------------------------------
// RoPE + split: g_qkv [B,S,3,H,DH] -> g_q/g_k (rotated), g_v, all [B,H,S,DH]
// Angles computed in double (well within the checker tolerance vs fp32 jax).
// One thread per (b,h,s,pair).
// ---------------------------------------------------------------------------
__global__ void rope_split_kernel()
{
    int idx = blockIdx.x * blockDim.x + threadIdx.x;
    if (idx >= B_ * H_ * S_ * (DH_ / 2)) return;
    const int p = idx & 31;           // pair index 0..31
    int t = idx >> 5;
    const int s = t & (S_ - 1);       // S_ = 2048
    t >>= 11;
    const int h = t & (H_ - 1);
    const int b = t >> 4;

    const size_t row = (size_t)(b * S_ + s) * (3 * D_) + h * DH_;
    const float qe = g_qkv[row + 2 * p],            qo = g_qkv[row + 2 * p + 1];
    const float ke = g_qkv[row + D_ + 2 * p],       ko = g_qkv[row + D_ + 2 * p + 1];
    const float ve = g_qkv[row + 2 * D_ + 2 * p],   vo = g_qkv[row + 2 * D_ + 2 * p + 1];

    // inv_freq = theta^{-2p/64}; ang = s * inv_freq
    const double invf = exp(-9.210340371976184 * (double)(2 * p) / 64.0); // ln(10000)
    const double ang  = (double)s * invf;
    double sd, cd;
    sincos(ang, &sd, &cd);
    const float c = (float)cd, sn = (float)sd;

    const size_t o = ((size_t)(b * H_ + h) * S_ + s) * DH_;
    g_q[o + 2 * p]     = qe * c - qo * sn;
    g_q[o + 2 * p + 1] = qe * sn + qo * c;
    g_k[o + 2 * p]     = ke * c - ko * sn;
    g_k[o + 2 * p + 1] = ke * sn + ko * c;
    g_v[o + 2 * p]     = ve;
    g_v[o + 2 * p + 1] = vo;
}

// ---------------------------------------------------------------------------
// Causal flash attention, fp32. 64 query rows / CTA (1 row per thread),
// 64-key tiles. q[64] and o[64] live in registers; K/V/score tiles in smem.
// Score tile stored transposed (sP[j][tid]) -> conflict-free.
// Output written directly in [B,S,H*DH] layout (ready for the final GEMM).
// ---------------------------------------------------------------------------
__global__ __launch_bounds__(64)
void flash_kernel()
{
    __shared__ float sK[64][64];
    __shared__ float sV[64][64];
    __shared__ float sP[64][64];   // transposed scores

    const int tid = threadIdx.x;
    const int qb  = blockIdx.x;          // query block within S
    const int bh  = blockIdx.y;          // b*H + h
    const int qi  = qb * 64 + tid;       // global query row in [0,S)
    const float scale = 0.125f;          // 1/sqrt(64)

    const float* qptr = g_q + ((size_t)bh * S_ + qi) * DH_;
    float q[64], o[64];
#pragma unroll
    for (int i = 0; i < 16; i++) {
        float4 v = *reinterpret_cast<const float4*>(qptr + i * 4);
        q[4 * i]     = v.x * scale;
        q[4 * i + 1] = v.y * scale;
        q[4 * i + 2] = v.z * scale;
        q[4 * i + 3] = v.w * scale;
    }
#pragma unroll
    for (int d = 0; d < 64; d++) o[d] = 0.f;
    float m = -FLT_MAX, l = 0.f;

    for (int kb = 0; kb <= qb; kb++) {
        __syncthreads();   // previous iteration's sK/sV/sP reads are done
        const float* kg = g_k + ((size_t)bh * S_ + kb * 64) * DH_;
        const float* vg = g_v + ((size_t)bh * S_ + kb * 64) * DH_;
#pragma unroll
        for (int i = tid; i < 64 * 16; i += 64) {
            int r = i >> 4, c = (i & 15) * 4;
            *reinterpret_cast<float4*>(&sK[r][c]) =
                *reinterpret_cast<const float4*>(kg + r * DH_ + c);
            *reinterpret_cast<float4*>(&sV[r][c]) =
                *reinterpret_cast<const float4*>(vg + r * DH_ + c);
        }
        __syncthreads();

        const bool diag = (kb == qb);
        float smax = -FLT_MAX;
        for (int j = 0; j < 64; j++) {
            float s = 0.f;
#pragma unroll
            for (int i = 0; i < 16; i++) {
                float4 kv = *reinterpret_cast<const float4*>(&sK[j][i * 4]);
                s += q[4 * i] * kv.x + q[4 * i + 1] * kv.y
                   + q[4 * i + 2] * kv.z + q[4 * i + 3] * kv.w;
            }
            if (diag && j > tid) s = -FLT_MAX;   // causal mask (only diagonal block)
            sP[j][tid] = s;
            smax = fmaxf(smax, s);
        }

        const float mnew = fmaxf(m, smax);
        const float corr = __expf(m - mnew);
        l *= corr;
#pragma unroll
        for (int d = 0; d < 64; d++) o[d] *= corr;

        for (int j = 0; j < 64; j++) {
            float p = __expf(sP[j][tid] - mnew);
            l += p;
#pragma unroll
            for (int i = 0; i < 16; i++) {
                float4 vv = *reinterpret_cast<const float4*>(&sV[j][i * 4]);
                o[4 * i]     += p * vv.x;
                o[4 * i + 1] += p * vv.y;
                o[4 * i + 2] += p * vv.z;
                o[4 * i + 3] += p * vv.w;
            }
        }
        m = mnew;
    }

    const float inv = 1.f / l;
    const int b = bh >> 4, h = bh & 15;
    float* op = g_attn + ((size_t)(b * S_ + qi)) * D_ + h * DH_;
#pragma unroll
    for (int i = 0; i < 16; i++) {
        float4 v = make_float4(o[4 * i] * inv, o[4 * i + 1] * inv,
                               o[4 * i + 2] * inv, o[4 * i + 3] * inv);
        *reinterpret_cast<float4*>(op + i * 4) = v;
    }
}

// ---------------------------------------------------------------------------
extern "C" void kernel_launch(void* const* d_in, const int* in_sizes, int n_in,
                              void* d_out, int out_size)
{
    const float* X    = (const float*)d_in[0];   // [B,S,D]
    const float* Wqkv = (const float*)d_in[1];   // [3D,D]
    const float* Wo   = (const float*)d_in[2];   // [D,D]
    float* out = (float*)d_out;                  // [B,S,D]
    (void)in_sizes; (void)n_in; (void)out_size;

    float *qkvp = nullptr, *attnp = nullptr;
    cudaGetSymbolAddress((void**)&qkvp, g_qkv);
    cudaGetSymbolAddress((void**)&attnp, g_attn);

    // 1) QKV projection: [4096,1024] x [3072,1024]^T -> [4096,3072]
    {
        dim3 grid(3 * D_ / 64, M_ / 64);  // (48, 64)
        gemm_nt_kernel<<<grid, 128>>>(X, Wqkv, qkvp, M_, 3 * D_, D_);
    }
    // 2) RoPE + split into Q/K/V [B,H,S,DH]
    {
        int total = B_ * H_ * S_ * (DH_ / 2);    // 2,097,152
        rope_split_kernel<<<total / 256, 256>>>();
    }
    // 3) Causal flash attention -> g_attn [B,S,D]
    {
        dim3 grid(S_ / 64, B_ * H_);   // (32, 32)
        flash_kernel<<<grid, 64>>>();
    }
    // 4) Output projection: [4096,1024] x [1024,1024]^T -> d_out
    {
        dim3 grid(D_ / 64, M_ / 64);   // (16, 64)
        gemm_nt_kernel<<<grid, 128>>>(attnp, Wo, out, M_, D_, D_);
    }
}

// round 2
// speedup vs baseline: 1.1684x; 1.1684x over previous
#include <cuda_runtime.h>
#include <math.h>
#include <float.h>

namespace {
constexpr int B_  = 2;
constexpr int S_  = 2048;
constexpr int D_  = 1024;
constexpr int H_  = 16;
constexpr int DH_ = 64;
constexpr int M_  = B_ * S_;          // 4096
}

// Scratch (device globals — allocation is forbidden)
__device__ float g_qkv[(size_t)M_ * 3 * D_];           // [B,S,3,H,DH]
__device__ float g_q[(size_t)B_ * H_ * S_ * DH_];      // [B,H,S,DH]
__device__ float g_k[(size_t)B_ * H_ * S_ * DH_];
__device__ float g_v[(size_t)B_ * H_ * S_ * DH_];
__device__ float g_attn[(size_t)M_ * D_];              // [B,S,D]

// ---------------------------------------------------------------------------
// C[M,N] = A[M,K] * W[N,K]^T.  128x128 tile, BK=16, 256 threads, 8x8 fragment,
// register prefetch double-buffering.
// ---------------------------------------------------------------------------
__global__ __launch_bounds__(256)
void gemm_nt_kernel(const float* __restrict__ A, const float* __restrict__ W,
                    float* __restrict__ C, int M, int N, int K)
{
    constexpr int BM = 128, BN = 128, BK = 16;
    __shared__ float As[BK][BM + 4];
    __shared__ float Bs[BK][BN + 4];

    const int tid = threadIdx.x;
    const int bm  = blockIdx.y * BM;
    const int bn  = blockIdx.x * BN;
    const int ty  = tid >> 4;   // 0..15 -> 8 rows each
    const int tx  = tid & 15;   // 0..15 -> 8 cols each

    const int lr = tid >> 2;          // 0..63
    const int lq = (tid & 3) * 4;     // 0,4,8,12

    float acc[8][8];
#pragma unroll
    for (int i = 0; i < 8; i++)
#pragma unroll
        for (int j = 0; j < 8; j++) acc[i][j] = 0.f;

    const float* Ar0 = A + (size_t)(bm + lr) * K + lq;
    const float* Ar1 = A + (size_t)(bm + lr + 64) * K + lq;
    const float* Wr0 = W + (size_t)(bn + lr) * K + lq;
    const float* Wr1 = W + (size_t)(bn + lr + 64) * K + lq;

    float4 pa0 = *reinterpret_cast<const float4*>(Ar0);
    float4 pa1 = *reinterpret_cast<const float4*>(Ar1);
    float4 pb0 = *reinterpret_cast<const float4*>(Wr0);
    float4 pb1 = *reinterpret_cast<const float4*>(Wr1);

    auto store_tiles = [&](float4 a0, float4 a1, float4 b0, float4 b1) {
        As[lq + 0][lr] = a0.x; As[lq + 1][lr] = a0.y;
        As[lq + 2][lr] = a0.z; As[lq + 3][lr] = a0.w;
        As[lq + 0][lr + 64] = a1.x; As[lq + 1][lr + 64] = a1.y;
        As[lq + 2][lr + 64] = a1.z; As[lq + 3][lr + 64] = a1.w;
        Bs[lq + 0][lr] = b0.x; Bs[lq + 1][lr] = b0.y;
        Bs[lq + 2][lr] = b0.z; Bs[lq + 3][lr] = b0.w;
        Bs[lq + 0][lr + 64] = b1.x; Bs[lq + 1][lr + 64] = b1.y;
        Bs[lq + 2][lr + 64] = b1.z; Bs[lq + 3][lr + 64] = b1.w;
    };
    auto compute = [&]() {
#pragma unroll
        for (int k = 0; k < BK; k++) {
            float4 a0 = *reinterpret_cast<const float4*>(&As[k][ty * 8]);
            float4 a1 = *reinterpret_cast<const float4*>(&As[k][ty * 8 + 4]);
            float4 b0 = *reinterpret_cast<const float4*>(&Bs[k][tx * 8]);
            float4 b1 = *reinterpret_cast<const float4*>(&Bs[k][tx * 8 + 4]);
            float av[8] = {a0.x, a0.y, a0.z, a0.w, a1.x, a1.y, a1.z, a1.w};
            float bv[8] = {b0.x, b0.y, b0.z, b0.w, b1.x, b1.y, b1.z, b1.w};
#pragma unroll
            for (int i = 0; i < 8; i++)
#pragma unroll
                for (int j = 0; j < 8; j++)
                    acc[i][j] += av[i] * bv[j];
        }
    };

    store_tiles(pa0, pa1, pb0, pb1);
    __syncthreads();

    for (int k0 = BK; k0 < K; k0 += BK) {
        float4 na0 = *reinterpret_cast<const float4*>(Ar0 + k0);
        float4 na1 = *reinterpret_cast<const float4*>(Ar1 + k0);
        float4 nb0 = *reinterpret_cast<const float4*>(Wr0 + k0);
        float4 nb1 = *reinterpret_cast<const float4*>(Wr1 + k0);
        compute();
        __syncthreads();
        store_tiles(na0, na1, nb0, nb1);
        __syncthreads();
    }
    compute();

#pragma unroll
    for (int i = 0; i < 8; i++) {
        float* crow = C + (size_t)(bm + ty * 8 + i) * N + bn + tx * 8;
        *reinterpret_cast<float4*>(crow) =
            make_float4(acc[i][0], acc[i][1], acc[i][2], acc[i][3]);
        *reinterpret_cast<float4*>(crow + 4) =
            make_float4(acc[i][4], acc[i][5], acc[i][6], acc[i][7]);
    }
}

// ---------------------------------------------------------------------------
// RoPE + split: g_qkv [B,S,3,H,DH] -> g_q/g_k (rotated), g_v, all [B,H,S,DH]
// ---------------------------------------------------------------------------
__global__ void rope_split_kernel()
{
    int idx = blockIdx.x * blockDim.x + threadIdx.x;
    if (idx >= B_ * H_ * S_ * (DH_ / 2)) return;
    const int p = idx & 31;
    int t = idx >> 5;
    const int s = t & (S_ - 1);
    t >>= 11;
    const int h = t & (H_ - 1);
    const int b = t >> 4;

    const size_t row = (size_t)(b * S_ + s) * (3 * D_) + h * DH_;
    const float qe = g_qkv[row + 2 * p],          qo = g_qkv[row + 2 * p + 1];
    const float ke = g_qkv[row + D_ + 2 * p],     ko = g_qkv[row + D_ + 2 * p + 1];
    const float ve = g_qkv[row + 2 * D_ + 2 * p], vo = g_qkv[row + 2 * D_ + 2 * p + 1];

    const double invf = exp(-9.210340371976184 * (double)(2 * p) / 64.0);
    const double ang  = (double)s * invf;
    double sd, cd;
    sincos(ang, &sd, &cd);
    const float c = (float)cd, sn = (float)sd;

    const size_t o = ((size_t)(b * H_ + h) * S_ + s) * DH_;
    g_q[o + 2 * p]     = qe * c - qo * sn;
    g_q[o + 2 * p + 1] = qe * sn + qo * c;
    g_k[o + 2 * p]     = ke * c - ko * sn;
    g_k[o + 2 * p + 1] = ke * sn + ko * c;
    g_v[o + 2 * p]     = ve;
    g_v[o + 2 * p + 1] = vo;
}

// ---------------------------------------------------------------------------
// Causal flash attention, fp32, register-fragment version.
// CTA: 64 queries, 128 threads (ty=tid>>4 owns 8 q-rows, tx=tid&15 owns 4 cols).
// Row-softmax reductions are in-warp shfl over the 16-lane row group; the
// thread's S rows == its O rows, so m/l/corr are thread-local.
// ---------------------------------------------------------------------------
__global__ __launch_bounds__(128)
void flash_kernel()
{
    extern __shared__ float sm[];
    float* sQT = sm;                   // [64 d][68]  (q-index contiguous)
    float* sKT = sm + 64 * 68;         // [64 d][68]  (k-index contiguous)
    float* sV  = sm + 2 * 64 * 68;     // [64 k][68]  (d contiguous)
    float* sP  = sm + 3 * 64 * 68;     // [64 q][68]  (k contiguous)

    const int tid = threadIdx.x;
    const int ty  = tid >> 4;          // 0..7
    const int tx  = tid & 15;          // 0..15
    const int qb  = gridDim.x - 1 - blockIdx.x;  // long CTAs first
    const int bh  = blockIdx.y;
    const float scale = 0.125f;

    // Load Q tile transposed & pre-scaled: sQT[d][q]
    const float* qg = g_q + ((size_t)bh * S_ + qb * 64) * DH_;
#pragma unroll
    for (int t = 0; t < 8; t++) {
        int i = tid + t * 128;         // 0..1023 float4s
        int r = i >> 4, c = (i & 15) * 4;
        float4 v = *reinterpret_cast<const float4*>(qg + r * DH_ + c);
        sQT[(c + 0) * 68 + r] = v.x * scale;
        sQT[(c + 1) * 68 + r] = v.y * scale;
        sQT[(c + 2) * 68 + r] = v.z * scale;
        sQT[(c + 3) * 68 + r] = v.w * scale;
    }

    float O[8][4];
    float m[8], l[8];
#pragma unroll
    for (int i = 0; i < 8; i++) {
        m[i] = -1e30f; l[i] = 0.f;
#pragma unroll
        for (int j = 0; j < 4; j++) O[i][j] = 0.f;
    }

    for (int kb = 0; kb <= qb; kb++) {
        __syncthreads();   // prior tile's sKT/sV/sP reads complete
        const float* kg = g_k + ((size_t)bh * S_ + kb * 64) * DH_;
        const float* vg = g_v + ((size_t)bh * S_ + kb * 64) * DH_;
#pragma unroll
        for (int t = 0; t < 8; t++) {
            int i = tid + t * 128;
            int r = i >> 4, c = (i & 15) * 4;
            float4 kv = *reinterpret_cast<const float4*>(kg + r * DH_ + c);
            sKT[(c + 0) * 68 + r] = kv.x;
            sKT[(c + 1) * 68 + r] = kv.y;
            sKT[(c + 2) * 68 + r] = kv.z;
            sKT[(c + 3) * 68 + r] = kv.w;
            float4 vv = *reinterpret_cast<const float4*>(vg + r * DH_ + c);
            *reinterpret_cast<float4*>(&sV[r * 68 + c]) = vv;
        }
        __syncthreads();

        // S fragment = Q K^T  (8 rows x 4 cols per thread)
        float s[8][4];
#pragma unroll
        for (int i = 0; i < 8; i++)
#pragma unroll
            for (int j = 0; j < 4; j++) s[i][j] = 0.f;

#pragma unroll 4
        for (int d = 0; d < 64; d++) {
            float4 a0 = *reinterpret_cast<const float4*>(&sQT[d * 68 + ty * 8]);
            float4 a1 = *reinterpret_cast<const float4*>(&sQT[d * 68 + ty * 8 + 4]);
            float4 b  = *reinterpret_cast<const float4*>(&sKT[d * 68 + tx * 4]);
            float av[8] = {a0.x, a0.y, a0.z, a0.w, a1.x, a1.y, a1.z, a1.w};
            float bv[4] = {b.x, b.y, b.z, b.w};
#pragma unroll
            for (int i = 0; i < 8; i++)
#pragma unroll
                for (int j = 0; j < 4; j++)
                    s[i][j] += av[i] * bv[j];
        }

        if (kb == qb) {   // causal mask on the diagonal tile
#pragma unroll
            for (int i = 0; i < 8; i++)
#pragma unroll
                for (int j = 0; j < 4; j++)
                    if (tx * 4 + j > ty * 8 + i) s[i][j] = -1e30f;
        }

        // Row max across thread (4 cols) then across 16-lane row group.
        float tm[8];
#pragma unroll
        for (int i = 0; i < 8; i++)
            tm[i] = fmaxf(fmaxf(s[i][0], s[i][1]), fmaxf(s[i][2], s[i][3]));
#pragma unroll
        for (int off = 1; off < 16; off <<= 1)
#pragma unroll
            for (int i = 0; i < 8; i++)
                tm[i] = fmaxf(tm[i], __shfl_xor_sync(0xffffffffu, tm[i], off));

        float corr[8];
#pragma unroll
        for (int i = 0; i < 8; i++) {
            float mn = fmaxf(m[i], tm[i]);
            corr[i] = __expf(m[i] - mn);
            m[i] = mn;
        }

        float rs[8];
#pragma unroll
        for (int i = 0; i < 8; i++) {
            float p0 = __expf(s[i][0] - m[i]);
            float p1 = __expf(s[i][1] - m[i]);
            float p2 = __expf(s[i][2] - m[i]);
            float p3 = __expf(s[i][3] - m[i]);
            s[i][0] = p0; s[i][1] = p1; s[i][2] = p2; s[i][3] = p3;
            rs[i] = (p0 + p1) + (p2 + p3);
        }
#pragma unroll
        for (int off = 1; off < 16; off <<= 1)
#pragma unroll
            for (int i = 0; i < 8; i++)
                rs[i] += __shfl_xor_sync(0xffffffffu, rs[i], off);

#pragma unroll
        for (int i = 0; i < 8; i++) {
            l[i] = l[i] * corr[i] + rs[i];
#pragma unroll
            for (int j = 0; j < 4; j++) O[i][j] *= corr[i];
            *reinterpret_cast<float4*>(&sP[(ty * 8 + i) * 68 + tx * 4]) =
                make_float4(s[i][0], s[i][1], s[i][2], s[i][3]);
        }
        __syncthreads();

        // O += P V  (rows = same 8 q-rows, cols = tx*4..+3 of d)
#pragma unroll 4
        for (int k = 0; k < 64; k++) {
            float4 b = *reinterpret_cast<const float4*>(&sV[k * 68 + tx * 4]);
#pragma unroll
            for (int i = 0; i < 8; i++) {
                float a = sP[(ty * 8 + i) * 68 + k];
                O[i][0] += a * b.x;
                O[i][1] += a * b.y;
                O[i][2] += a * b.z;
                O[i][3] += a * b.w;
            }
        }
    }

    const int b = bh >> 4, h = bh & 15;
#pragma unroll
    for (int i = 0; i < 8; i++) {
        float inv = 1.f / l[i];
        int q = qb * 64 + ty * 8 + i;
        float* op = g_attn + (size_t)(b * S_ + q) * D_ + h * 64 + tx * 4;
        *reinterpret_cast<float4*>(op) =
            make_float4(O[i][0] * inv, O[i][1] * inv, O[i][2] * inv, O[i][3] * inv);
    }
}

// ---------------------------------------------------------------------------
extern "C" void kernel_launch(void* const* d_in, const int* in_sizes, int n_in,
                              void* d_out, int out_size)
{
    const float* X    = (const float*)d_in[0];
    const float* Wqkv = (const float*)d_in[1];
    const float* Wo   = (const float*)d_in[2];
    float* out = (float*)d_out;
    (void)in_sizes; (void)n_in; (void)out_size;

    float *qkvp = nullptr, *attnp = nullptr;
    cudaGetSymbolAddress((void**)&qkvp, g_qkv);
    cudaGetSymbolAddress((void**)&attnp, g_attn);

    const int flash_smem = 4 * 64 * 68 * 4;   // 69632 B
    cudaFuncSetAttribute(flash_kernel,
                         cudaFuncAttributeMaxDynamicSharedMemorySize, flash_smem);

    // 1) QKV projection: [4096,1024] x [3072,1024]^T
    {
        dim3 grid(3 * D_ / 128, M_ / 128);  // (24, 32)
        gemm_nt_kernel<<<grid, 256>>>(X, Wqkv, qkvp, M_, 3 * D_, D_);
    }
    // 2) RoPE + split
    {
        int total = B_ * H_ * S_ * (DH_ / 2);
        rope_split_kernel<<<total / 256, 256>>>();
    }
    // 3) Causal flash attention
    {
        dim3 grid(S_ / 64, B_ * H_);   // (32, 32)
        flash_kernel<<<grid, 128, flash_smem>>>();
    }
    // 4) Output projection
    {
        dim3 grid(D_ / 128, M_ / 128); // (8, 32)
        gemm_nt_kernel<<<grid, 256>>>(attnp, Wo, out, M_, D_, D_);
    }
}

// round 4
// speedup vs baseline: 1.4647x; 1.2537x over previous
#include <cuda_runtime.h>
#include <cuda_bf16.h>
#include <math.h>
#include <float.h>
#include <stdint.h>

namespace {
constexpr int B_  = 2;
constexpr int S_  = 2048;
constexpr int D_  = 1024;
constexpr int H_  = 16;
constexpr int DH_ = 64;
constexpr int M_  = B_ * S_;          // 4096
}

// Scratch (device globals — allocation is forbidden)
__device__ float g_qkv[(size_t)M_ * 3 * D_];           // [B,S,3,H,DH]
__device__ float g_q[(size_t)B_ * H_ * S_ * DH_];      // [B,H,S,DH]
__device__ float g_k[(size_t)B_ * H_ * S_ * DH_];
__device__ float g_v[(size_t)B_ * H_ * S_ * DH_];
__device__ float g_attn[(size_t)M_ * D_];              // [B,S,D]

// Packed bf16x2 hi/lo split operands (pairs along K)
__device__ uint32_t g_Xhi[(size_t)M_ * D_ / 2],  g_Xlo[(size_t)M_ * D_ / 2];
__device__ uint32_t g_W1hi[(size_t)3 * D_ * D_ / 2], g_W1lo[(size_t)3 * D_ * D_ / 2];
__device__ uint32_t g_W2hi[(size_t)D_ * D_ / 2], g_W2lo[(size_t)D_ * D_ / 2];
__device__ uint32_t g_AThi[(size_t)M_ * D_ / 2], g_ATlo[(size_t)M_ * D_ / 2];

// ---------------------------------------------------------------------------
// bf16 split helpers
// ---------------------------------------------------------------------------
__device__ __forceinline__ void split2(float a, float b, uint32_t& h, uint32_t& l)
{
    __nv_bfloat16 ha = __float2bfloat16(a), hb = __float2bfloat16(b);
    float ra = a - __bfloat162float(ha);
    float rb = b - __bfloat162float(hb);
    __nv_bfloat16 la = __float2bfloat16(ra), lb = __float2bfloat16(rb);
    h = ((uint32_t)__bfloat16_as_ushort(hb) << 16) | (uint32_t)__bfloat16_as_ushort(ha);
    l = ((uint32_t)__bfloat16_as_ushort(lb) << 16) | (uint32_t)__bfloat16_as_ushort(la);
}

// Convert float array -> packed bf16x2 hi/lo (pairs of consecutive elements)
__global__ void convert_kernel(const float* __restrict__ src,
                               uint32_t* __restrict__ hi,
                               uint32_t* __restrict__ lo, int n4)
{
    int i = blockIdx.x * blockDim.x + threadIdx.x;
    if (i >= n4) return;
    float4 x = reinterpret_cast<const float4*>(src)[i];
    uint2 h, l;
    split2(x.x, x.y, h.x, l.x);
    split2(x.z, x.w, h.y, l.y);
    reinterpret_cast<uint2*>(hi)[i] = h;
    reinterpret_cast<uint2*>(lo)[i] = l;
}

// mma.sync m16n8k16 bf16, fp32 accumulate (works on base sm_103 target)
__device__ __forceinline__ void mma_bf16(float c[4],
                                         uint32_t a0, uint32_t a1,
                                         uint32_t a2, uint32_t a3,
                                         uint32_t b0, uint32_t b1)
{
    asm volatile(
        "mma.sync.aligned.m16n8k16.row.col.f32.bf16.bf16.f32 "
        "{%0,%1,%2,%3}, {%4,%5,%6,%7}, {%8,%9}, {%0,%1,%2,%3};"
        : "+f"(c[0]), "+f"(c[1]), "+f"(c[2]), "+f"(c[3])
        : "r"(a0), "r"(a1), "r"(a2), "r"(a3), "r"(b0), "r"(b1));
}

// ---------------------------------------------------------------------------
// C[M,N] = A[M,K] * W[N,K]^T via bf16x3 mma.sync emulation of fp32.
// Inputs are pre-split packed bf16x2 (K2 = K/2 pairs per row).
// 128x128 CTA tile, 8 warps (4 m x 2 n), warp tile 32x64, chunk = 16 pairs.
// ---------------------------------------------------------------------------
__global__ __launch_bounds__(256)
void gemm_mma_kernel(const uint32_t* __restrict__ Ahi, const uint32_t* __restrict__ Alo,
                     const uint32_t* __restrict__ Bhi, const uint32_t* __restrict__ Blo,
                     float* __restrict__ C, int M, int N, int K2)
{
    constexpr int PAD = 20;              // u32 per smem row (16 + 4 pad): conflict-free
    __shared__ uint32_t sAhi[128 * PAD], sAlo[128 * PAD];
    __shared__ uint32_t sBhi[128 * PAD], sBlo[128 * PAD];

    const int tid  = threadIdx.x;
    const int wid  = tid >> 5;
    const int lane = tid & 31;
    const int g    = lane >> 2;          // 0..7
    const int t    = lane & 3;           // 0..3
    const int wm   = wid & 3;            // 4 warps over M (32 rows each)
    const int wn   = wid >> 2;           // 2 warps over N (64 cols each)
    const int bm   = blockIdx.y * 128;
    const int bn   = blockIdx.x * 128;

    float c[2][8][4];
#pragma unroll
    for (int mi = 0; mi < 2; mi++)
#pragma unroll
        for (int nj = 0; nj < 8; nj++)
#pragma unroll
            for (int k = 0; k < 4; k++) c[mi][nj][k] = 0.f;

    const int nchunks = K2 >> 4;         // 16 pairs per chunk
    for (int cc = 0; cc < nchunks; cc++) {
        const int kp = cc << 4;
        // Fill smem: 512 uint4 per buffer; 2 per thread per buffer.
#pragma unroll
        for (int i = 0; i < 2; i++) {
            const int v = tid + (i << 8);      // 0..511
            const int r = v >> 2;              // row 0..127
            const int j = (v & 3) << 2;        // pair offset 0,4,8,12
            const size_t ga = (size_t)(bm + r) * K2 + kp + j;
            const size_t gb = (size_t)(bn + r) * K2 + kp + j;
            *reinterpret_cast<uint4*>(&sAhi[r * PAD + j]) =
                *reinterpret_cast<const uint4*>(Ahi + ga);
            *reinterpret_cast<uint4*>(&sAlo[r * PAD + j]) =
                *reinterpret_cast<const uint4*>(Alo + ga);
            *reinterpret_cast<uint4*>(&sBhi[r * PAD + j]) =
                *reinterpret_cast<const uint4*>(Bhi + gb);
            *reinterpret_cast<uint4*>(&sBlo[r * PAD + j]) =
                *reinterpret_cast<const uint4*>(Blo + gb);
        }
        __syncthreads();

#pragma unroll
        for (int step = 0; step < 2; step++) {
            const int ko = step << 3;          // pair offset 0 or 8
            uint32_t aH[2][4], aL[2][4];
#pragma unroll
            for (int mi = 0; mi < 2; mi++) {
                const int r0 = (wm * 32 + mi * 16 + g) * PAD + ko + t;
                const int r1 = (wm * 32 + mi * 16 + 8 + g) * PAD + ko + t;
                aH[mi][0] = sAhi[r0];     aH[mi][1] = sAhi[r1];
                aH[mi][2] = sAhi[r0 + 4]; aH[mi][3] = sAhi[r1 + 4];
                aL[mi][0] = sAlo[r0];     aL[mi][1] = sAlo[r1];
                aL[mi][2] = sAlo[r0 + 4]; aL[mi][3] = sAlo[r1 + 4];
            }
#pragma unroll
            for (int nj = 0; nj < 8; nj++) {
                const int nb = (wn * 64 + nj * 8 + g) * PAD + ko + t;
                const uint32_t bH0 = sBhi[nb], bH1 = sBhi[nb + 4];
                const uint32_t bL0 = sBlo[nb], bL1 = sBlo[nb + 4];
#pragma unroll
                for (int mi = 0; mi < 2; mi++) {
                    mma_bf16(c[mi][nj], aH[mi][0], aH[mi][1], aH[mi][2], aH[mi][3], bH0, bH1);
                    mma_bf16(c[mi][nj], aH[mi][0], aH[mi][1], aH[mi][2], aH[mi][3], bL0, bL1);
                    mma_bf16(c[mi][nj], aL[mi][0], aL[mi][1], aL[mi][2], aL[mi][3], bH0, bH1);
                }
            }
        }
        __syncthreads();
    }

#pragma unroll
    for (int mi = 0; mi < 2; mi++) {
        const int row = bm + wm * 32 + mi * 16 + g;
#pragma unroll
        for (int nj = 0; nj < 8; nj++) {
            const int col = bn + wn * 64 + nj * 8 + 2 * t;
            *reinterpret_cast<float2*>(C + (size_t)row * N + col) =
                make_float2(c[mi][nj][0], c[mi][nj][1]);
            *reinterpret_cast<float2*>(C + (size_t)(row + 8) * N + col) =
                make_float2(c[mi][nj][2], c[mi][nj][3]);
        }
    }
}

// ---------------------------------------------------------------------------
// RoPE + split: g_qkv [B,S,3,H,DH] -> g_q/g_k (rotated), g_v, all [B,H,S,DH]
// ---------------------------------------------------------------------------
__global__ void rope_split_kernel()
{
    int idx = blockIdx.x * blockDim.x + threadIdx.x;
    if (idx >= B_ * H_ * S_ * (DH_ / 2)) return;
    const int p = idx & 31;
    int t = idx >> 5;
    const int s = t & (S_ - 1);
    t >>= 11;
    const int h = t & (H_ - 1);
    const int b = t >> 4;

    const size_t row = (size_t)(b * S_ + s) * (3 * D_) + h * DH_;
    const float qe = g_qkv[row + 2 * p],          qo = g_qkv[row + 2 * p + 1];
    const float ke = g_qkv[row + D_ + 2 * p],     ko = g_qkv[row + D_ + 2 * p + 1];
    const float ve = g_qkv[row + 2 * D_ + 2 * p], vo = g_qkv[row + 2 * D_ + 2 * p + 1];

    const double invf = exp(-9.210340371976184 * (double)(2 * p) / 64.0);
    const double ang  = (double)s * invf;
    double sd, cd;
    sincos(ang, &sd, &cd);
    const float c = (float)cd, sn = (float)sd;

    const size_t o = ((size_t)(b * H_ + h) * S_ + s) * DH_;
    g_q[o + 2 * p]     = qe * c - qo * sn;
    g_q[o + 2 * p + 1] = qe * sn + qo * c;
    g_k[o + 2 * p]     = ke * c - ko * sn;
    g_k[o + 2 * p + 1] = ke * sn + ko * c;
    g_v[o + 2 * p]     = ve;
    g_v[o + 2 * p + 1] = vo;
}

// ---------------------------------------------------------------------------
// Causal flash attention, fp32, register-fragment version (unchanged, R2).
// ---------------------------------------------------------------------------
__global__ __launch_bounds__(128)
void flash_kernel()
{
    extern __shared__ float sm[];
    float* sQT = sm;                   // [64 d][68]
    float* sKT = sm + 64 * 68;         // [64 d][68]
    float* sV  = sm + 2 * 64 * 68;     // [64 k][68]
    float* sP  = sm + 3 * 64 * 68;     // [64 q][68]

    const int tid = threadIdx.x;
    const int ty  = tid >> 4;
    const int tx  = tid & 15;
    const int qb  = gridDim.x - 1 - blockIdx.x;
    const int bh  = blockIdx.y;
    const float scale = 0.125f;

    const float* qg = g_q + ((size_t)bh * S_ + qb * 64) * DH_;
#pragma unroll
    for (int t = 0; t < 8; t++) {
        int i = tid + t * 128;
        int r = i >> 4, c = (i & 15) * 4;
        float4 v = *reinterpret_cast<const float4*>(qg + r * DH_ + c);
        sQT[(c + 0) * 68 + r] = v.x * scale;
        sQT[(c + 1) * 68 + r] = v.y * scale;
        sQT[(c + 2) * 68 + r] = v.z * scale;
        sQT[(c + 3) * 68 + r] = v.w * scale;
    }

    float O[8][4];
    float m[8], l[8];
#pragma unroll
    for (int i = 0; i < 8; i++) {
        m[i] = -1e30f; l[i] = 0.f;
#pragma unroll
        for (int j = 0; j < 4; j++) O[i][j] = 0.f;
    }

    for (int kb = 0; kb <= qb; kb++) {
        __syncthreads();
        const float* kg = g_k + ((size_t)bh * S_ + kb * 64) * DH_;
        const float* vg = g_v + ((size_t)bh * S_ + kb * 64) * DH_;
#pragma unroll
        for (int t = 0; t < 8; t++) {
            int i = tid + t * 128;
            int r = i >> 4, c = (i & 15) * 4;
            float4 kv = *reinterpret_cast<const float4*>(kg + r * DH_ + c);
            sKT[(c + 0) * 68 + r] = kv.x;
            sKT[(c + 1) * 68 + r] = kv.y;
            sKT[(c + 2) * 68 + r] = kv.z;
            sKT[(c + 3) * 68 + r] = kv.w;
            float4 vv = *reinterpret_cast<const float4*>(vg + r * DH_ + c);
            *reinterpret_cast<float4*>(&sV[r * 68 + c]) = vv;
        }
        __syncthreads();

        float s[8][4];
#pragma unroll
        for (int i = 0; i < 8; i++)
#pragma unroll
            for (int j = 0; j < 4; j++) s[i][j] = 0.f;

#pragma unroll 4
        for (int d = 0; d < 64; d++) {
            float4 a0 = *reinterpret_cast<const float4*>(&sQT[d * 68 + ty * 8]);
            float4 a1 = *reinterpret_cast<const float4*>(&sQT[d * 68 + ty * 8 + 4]);
            float4 b  = *reinterpret_cast<const float4*>(&sKT[d * 68 + tx * 4]);
            float av[8] = {a0.x, a0.y, a0.z, a0.w, a1.x, a1.y, a1.z, a1.w};
            float bv[4] = {b.x, b.y, b.z, b.w};
#pragma unroll
            for (int i = 0; i < 8; i++)
#pragma unroll
                for (int j = 0; j < 4; j++)
                    s[i][j] += av[i] * bv[j];
        }

        if (kb == qb) {
#pragma unroll
            for (int i = 0; i < 8; i++)
#pragma unroll
                for (int j = 0; j < 4; j++)
                    if (tx * 4 + j > ty * 8 + i) s[i][j] = -1e30f;
        }

        float tm[8];
#pragma unroll
        for (int i = 0; i < 8; i++)
            tm[i] = fmaxf(fmaxf(s[i][0], s[i][1]), fmaxf(s[i][2], s[i][3]));
#pragma unroll
        for (int off = 1; off < 16; off <<= 1)
#pragma unroll
            for (int i = 0; i < 8; i++)
                tm[i] = fmaxf(tm[i], __shfl_xor_sync(0xffffffffu, tm[i], off));

        float corr[8];
#pragma unroll
        for (int i = 0; i < 8; i++) {
            float mn = fmaxf(m[i], tm[i]);
            corr[i] = __expf(m[i] - mn);
            m[i] = mn;
        }

        float rs[8];
#pragma unroll
        for (int i = 0; i < 8; i++) {
            float p0 = __expf(s[i][0] - m[i]);
            float p1 = __expf(s[i][1] - m[i]);
            float p2 = __expf(s[i][2] - m[i]);
            float p3 = __expf(s[i][3] - m[i]);
            s[i][0] = p0; s[i][1] = p1; s[i][2] = p2; s[i][3] = p3;
            rs[i] = (p0 + p1) + (p2 + p3);
        }
#pragma unroll
        for (int off = 1; off < 16; off <<= 1)
#pragma unroll
            for (int i = 0; i < 8; i++)
                rs[i] += __shfl_xor_sync(0xffffffffu, rs[i], off);

#pragma unroll
        for (int i = 0; i < 8; i++) {
            l[i] = l[i] * corr[i] + rs[i];
#pragma unroll
            for (int j = 0; j < 4; j++) O[i][j] *= corr[i];
            *reinterpret_cast<float4*>(&sP[(ty * 8 + i) * 68 + tx * 4]) =
                make_float4(s[i][0], s[i][1], s[i][2], s[i][3]);
        }
        __syncthreads();

#pragma unroll 4
        for (int k = 0; k < 64; k++) {
            float4 b = *reinterpret_cast<const float4*>(&sV[k * 68 + tx * 4]);
#pragma unroll
            for (int i = 0; i < 8; i++) {
                float a = sP[(ty * 8 + i) * 68 + k];
                O[i][0] += a * b.x;
                O[i][1] += a * b.y;
                O[i][2] += a * b.z;
                O[i][3] += a * b.w;
            }
        }
    }

    const int b = bh >> 4, h = bh & 15;
#pragma unroll
    for (int i = 0; i < 8; i++) {
        float inv = 1.f / l[i];
        int q = qb * 64 + ty * 8 + i;
        float* op = g_attn + (size_t)(b * S_ + q) * D_ + h * 64 + tx * 4;
        *reinterpret_cast<float4*>(op) =
            make_float4(O[i][0] * inv, O[i][1] * inv, O[i][2] * inv, O[i][3] * inv);
    }
}

// ---------------------------------------------------------------------------
extern "C" void kernel_launch(void* const* d_in, const int* in_sizes, int n_in,
                              void* d_out, int out_size)
{
    const float* X    = (const float*)d_in[0];
    const float* Wqkv = (const float*)d_in[1];
    const float* Wo   = (const float*)d_in[2];
    float* out = (float*)d_out;
    (void)in_sizes; (void)n_in; (void)out_size;

    float *qkvp = nullptr, *attnp = nullptr;
    cudaGetSymbolAddress((void**)&qkvp, g_qkv);
    cudaGetSymbolAddress((void**)&attnp, g_attn);
    uint32_t *xhi, *xlo, *w1hi, *w1lo, *w2hi, *w2lo, *athi, *atlo;
    cudaGetSymbolAddress((void**)&xhi,  g_Xhi);
    cudaGetSymbolAddress((void**)&xlo,  g_Xlo);
    cudaGetSymbolAddress((void**)&w1hi, g_W1hi);
    cudaGetSymbolAddress((void**)&w1lo, g_W1lo);
    cudaGetSymbolAddress((void**)&w2hi, g_W2hi);
    cudaGetSymbolAddress((void**)&w2lo, g_W2lo);
    cudaGetSymbolAddress((void**)&athi, g_AThi);
    cudaGetSymbolAddress((void**)&atlo, g_ATlo);

    const int flash_smem = 4 * 64 * 68 * 4;
    cudaFuncSetAttribute(flash_kernel,
                         cudaFuncAttributeMaxDynamicSharedMemorySize, flash_smem);

    // 0) Split inputs into bf16 hi/lo
    {
        int n4 = M_ * D_ / 4;
        convert_kernel<<<n4 / 256, 256>>>(X, xhi, xlo, n4);
        n4 = 3 * D_ * D_ / 4;
        convert_kernel<<<n4 / 256, 256>>>(Wqkv, w1hi, w1lo, n4);
        n4 = D_ * D_ / 4;
        convert_kernel<<<n4 / 256, 256>>>(Wo, w2hi, w2lo, n4);
    }
    // 1) QKV projection (bf16x3 mma): [4096,1024] x [3072,1024]^T
    {
        dim3 grid(3 * D_ / 128, M_ / 128);  // (24, 32)
        gemm_mma_kernel<<<grid, 256>>>(xhi, xlo, w1hi, w1lo, qkvp, M_, 3 * D_, D_ / 2);
    }
    // 2) RoPE + split
    {
        int total = B_ * H_ * S_ * (DH_ / 2);
        rope_split_kernel<<<total / 256, 256>>>();
    }
    // 3) Causal flash attention (fp32 CUDA-core)
    {
        dim3 grid(S_ / 64, B_ * H_);
        flash_kernel<<<grid, 128, flash_smem>>>();
    }
    // 4) Output projection (bf16x3 mma)
    {
        int n4 = M_ * D_ / 4;
        convert_kernel<<<n4 / 256, 256>>>(attnp, athi, atlo, n4);
        dim3 grid(D_ / 128, M_ / 128);      // (8, 32)
        gemm_mma_kernel<<<grid, 256>>>(athi, atlo, w2hi, w2lo, out, M_, D_, D_ / 2);
    }
}

// round 5
// speedup vs baseline: 2.4013x; 1.6394x over previous
#include <cuda_runtime.h>
#include <cuda_bf16.h>
#include <math.h>
#include <float.h>
#include <stdint.h>

namespace {
constexpr int B_  = 2;
constexpr int S_  = 2048;
constexpr int D_  = 1024;
constexpr int H_  = 16;
constexpr int DH_ = 64;
constexpr int M_  = B_ * S_;          // 4096
constexpr int BH_ = B_ * H_;          // 32
}

// Scratch (device globals — allocation is forbidden)
__device__ float g_qkv[(size_t)M_ * 3 * D_];           // [B,S,3,H,DH]
__device__ float g_v[(size_t)BH_ * S_ * DH_];          // [bh][s][dh] fp32
__device__ float g_attn[(size_t)M_ * D_];              // [B,S,D]

// Packed bf16x2 hi/lo operands
__device__ uint32_t g_Xhi[(size_t)M_ * D_ / 2],  g_Xlo[(size_t)M_ * D_ / 2];
__device__ uint32_t g_W1hi[(size_t)3 * D_ * D_ / 2], g_W1lo[(size_t)3 * D_ * D_ / 2];
__device__ uint32_t g_W2hi[(size_t)D_ * D_ / 2], g_W2lo[(size_t)D_ * D_ / 2];
__device__ uint32_t g_AThi[(size_t)M_ * D_ / 2], g_ATlo[(size_t)M_ * D_ / 2];
// Attention operands: Q/K [bh][s][32 dh-pairs], VT [bh][d][1024 s-pairs]
__device__ uint32_t g_Qph[(size_t)BH_ * S_ * 32], g_Qpl[(size_t)BH_ * S_ * 32];
__device__ uint32_t g_Kph[(size_t)BH_ * S_ * 32], g_Kpl[(size_t)BH_ * S_ * 32];
__device__ uint32_t g_VTh[(size_t)BH_ * DH_ * (S_ / 2)], g_VTl[(size_t)BH_ * DH_ * (S_ / 2)];

// ---------------------------------------------------------------------------
// helpers
// ---------------------------------------------------------------------------
__device__ __forceinline__ void split2(float a, float b, uint32_t& h, uint32_t& l)
{
    __nv_bfloat16 ha = __float2bfloat16(a), hb = __float2bfloat16(b);
    float ra = a - __bfloat162float(ha);
    float rb = b - __bfloat162float(hb);
    __nv_bfloat16 la = __float2bfloat16(ra), lb = __float2bfloat16(rb);
    h = ((uint32_t)__bfloat16_as_ushort(hb) << 16) | (uint32_t)__bfloat16_as_ushort(ha);
    l = ((uint32_t)__bfloat16_as_ushort(lb) << 16) | (uint32_t)__bfloat16_as_ushort(la);
}

__global__ void convert_kernel(const float* __restrict__ src,
                               uint32_t* __restrict__ hi,
                               uint32_t* __restrict__ lo, int n4)
{
    int i = blockIdx.x * blockDim.x + threadIdx.x;
    if (i >= n4) return;
    float4 x = reinterpret_cast<const float4*>(src)[i];
    uint2 h, l;
    split2(x.x, x.y, h.x, l.x);
    split2(x.z, x.w, h.y, l.y);
    reinterpret_cast<uint2*>(hi)[i] = h;
    reinterpret_cast<uint2*>(lo)[i] = l;
}

// mma.sync m16n8k16 bf16, fp32 accumulate
__device__ __forceinline__ void mma_bf16(float c[4],
                                         uint32_t a0, uint32_t a1,
                                         uint32_t a2, uint32_t a3,
                                         uint32_t b0, uint32_t b1)
{
    asm volatile(
        "mma.sync.aligned.m16n8k16.row.col.f32.bf16.bf16.f32 "
        "{%0,%1,%2,%3}, {%4,%5,%6,%7}, {%8,%9}, {%0,%1,%2,%3};"
        : "+f"(c[0]), "+f"(c[1]), "+f"(c[2]), "+f"(c[3])
        : "r"(a0), "r"(a1), "r"(a2), "r"(a3), "r"(b0), "r"(b1));
}

// ---------------------------------------------------------------------------
// GEMM-NT via bf16x3 mma (unchanged structure, +min-blocks for 2 CTAs/SM)
// ---------------------------------------------------------------------------
__global__ __launch_bounds__(256, 2)
void gemm_mma_kernel(const uint32_t* __restrict__ Ahi, const uint32_t* __restrict__ Alo,
                     const uint32_t* __restrict__ Bhi, const uint32_t* __restrict__ Blo,
                     float* __restrict__ C, int M, int N, int K2)
{
    constexpr int PAD = 20;
    __shared__ uint32_t sAhi[128 * PAD], sAlo[128 * PAD];
    __shared__ uint32_t sBhi[128 * PAD], sBlo[128 * PAD];

    const int tid  = threadIdx.x;
    const int wid  = tid >> 5;
    const int lane = tid & 31;
    const int g    = lane >> 2;
    const int t    = lane & 3;
    const int wm   = wid & 3;
    const int wn   = wid >> 2;
    const int bm   = blockIdx.y * 128;
    const int bn   = blockIdx.x * 128;

    float c[2][8][4];
#pragma unroll
    for (int mi = 0; mi < 2; mi++)
#pragma unroll
        for (int nj = 0; nj < 8; nj++)
#pragma unroll
            for (int k = 0; k < 4; k++) c[mi][nj][k] = 0.f;

    const int nchunks = K2 >> 4;
    for (int cc = 0; cc < nchunks; cc++) {
        const int kp = cc << 4;
#pragma unroll
        for (int i = 0; i < 2; i++) {
            const int v = tid + (i << 8);
            const int r = v >> 2;
            const int j = (v & 3) << 2;
            const size_t ga = (size_t)(bm + r) * K2 + kp + j;
            const size_t gb = (size_t)(bn + r) * K2 + kp + j;
            *reinterpret_cast<uint4*>(&sAhi[r * PAD + j]) =
                *reinterpret_cast<const uint4*>(Ahi + ga);
            *reinterpret_cast<uint4*>(&sAlo[r * PAD + j]) =
                *reinterpret_cast<const uint4*>(Alo + ga);
            *reinterpret_cast<uint4*>(&sBhi[r * PAD + j]) =
                *reinterpret_cast<const uint4*>(Bhi + gb);
            *reinterpret_cast<uint4*>(&sBlo[r * PAD + j]) =
                *reinterpret_cast<const uint4*>(Blo + gb);
        }
        __syncthreads();

#pragma unroll
        for (int step = 0; step < 2; step++) {
            const int ko = step << 3;
            uint32_t aH[2][4], aL[2][4];
#pragma unroll
            for (int mi = 0; mi < 2; mi++) {
                const int r0 = (wm * 32 + mi * 16 + g) * PAD + ko + t;
                const int r1 = (wm * 32 + mi * 16 + 8 + g) * PAD + ko + t;
                aH[mi][0] = sAhi[r0];     aH[mi][1] = sAhi[r1];
                aH[mi][2] = sAhi[r0 + 4]; aH[mi][3] = sAhi[r1 + 4];
                aL[mi][0] = sAlo[r0];     aL[mi][1] = sAlo[r1];
                aL[mi][2] = sAlo[r0 + 4]; aL[mi][3] = sAlo[r1 + 4];
            }
#pragma unroll
            for (int nj = 0; nj < 8; nj++) {
                const int nb = (wn * 64 + nj * 8 + g) * PAD + ko + t;
                const uint32_t bH0 = sBhi[nb], bH1 = sBhi[nb + 4];
                const uint32_t bL0 = sBlo[nb], bL1 = sBlo[nb + 4];
#pragma unroll
                for (int mi = 0; mi < 2; mi++) {
                    mma_bf16(c[mi][nj], aH[mi][0], aH[mi][1], aH[mi][2], aH[mi][3], bH0, bH1);
                    mma_bf16(c[mi][nj], aH[mi][0], aH[mi][1], aH[mi][2], aH[mi][3], bL0, bL1);
                    mma_bf16(c[mi][nj], aL[mi][0], aL[mi][1], aL[mi][2], aL[mi][3], bH0, bH1);
                }
            }
        }
        __syncthreads();
    }

#pragma unroll
    for (int mi = 0; mi < 2; mi++) {
        const int row = bm + wm * 32 + mi * 16 + g;
#pragma unroll
        for (int nj = 0; nj < 8; nj++) {
            const int col = bn + wn * 64 + nj * 8 + 2 * t;
            *reinterpret_cast<float2*>(C + (size_t)row * N + col) =
                make_float2(c[mi][nj][0], c[mi][nj][1]);
            *reinterpret_cast<float2*>(C + (size_t)(row + 8) * N + col) =
                make_float2(c[mi][nj][2], c[mi][nj][3]);
        }
    }
}

// ---------------------------------------------------------------------------
// RoPE + split. Writes packed bf16 hi/lo Q (pre-scaled) and K, fp32 V.
// ---------------------------------------------------------------------------
__global__ void rope_split_kernel()
{
    int idx = blockIdx.x * blockDim.x + threadIdx.x;
    if (idx >= BH_ * S_ * 32) return;
    const int p = idx & 31;
    int t = idx >> 5;
    const int s = t & (S_ - 1);
    t >>= 11;
    const int h = t & (H_ - 1);
    const int b = t >> 4;
    const int bh = b * H_ + h;

    const size_t row = (size_t)(b * S_ + s) * (3 * D_) + h * DH_;
    const float qe = g_qkv[row + 2 * p],          qo = g_qkv[row + 2 * p + 1];
    const float ke = g_qkv[row + D_ + 2 * p],     ko = g_qkv[row + D_ + 2 * p + 1];
    const float ve = g_qkv[row + 2 * D_ + 2 * p], vo = g_qkv[row + 2 * D_ + 2 * p + 1];

    const double invf = exp(-9.210340371976184 * (double)(2 * p) / 64.0);
    const double ang  = (double)s * invf;
    double sd, cd;
    sincos(ang, &sd, &cd);
    const float c = (float)cd, sn = (float)sd;

    const size_t po = ((size_t)bh * S_ + s) * 32 + p;
    uint32_t h32, l32;
    split2(0.125f * (qe * c - qo * sn), 0.125f * (qe * sn + qo * c), h32, l32);
    g_Qph[po] = h32; g_Qpl[po] = l32;
    split2(ke * c - ko * sn, ke * sn + ko * c, h32, l32);
    g_Kph[po] = h32; g_Kpl[po] = l32;

    const size_t vo_ = ((size_t)bh * S_ + s) * DH_ + 2 * p;
    g_v[vo_]     = ve;
    g_v[vo_ + 1] = vo;
}

// ---------------------------------------------------------------------------
// V transpose + bf16 split: g_v [bh][s][d] -> VT [bh][d][spair] packed.
// ---------------------------------------------------------------------------
__global__ __launch_bounds__(256)
void vtrans_kernel()
{
    __shared__ float sv[64][65];
    const int tid = threadIdx.x;
    const int bh  = blockIdx.y;
    const int s0  = blockIdx.x * 64;

    const float* vg = g_v + ((size_t)bh * S_ + s0) * DH_;
#pragma unroll
    for (int i = 0; i < 4; i++) {
        int idx = tid + i * 256;           // 0..1023 float4
        int r = idx >> 4, c = (idx & 15) * 4;
        float4 v = *reinterpret_cast<const float4*>(vg + r * DH_ + c);
        sv[r][c] = v.x; sv[r][c + 1] = v.y; sv[r][c + 2] = v.z; sv[r][c + 3] = v.w;
    }
    __syncthreads();
#pragma unroll
    for (int i = 0; i < 8; i++) {
        int o = tid + i * 256;             // 0..2047
        int d = o >> 5, sp = o & 31;
        uint32_t h, l;
        split2(sv[2 * sp][d], sv[2 * sp + 1][d], h, l);
        size_t dst = ((size_t)bh * DH_ + d) * (S_ / 2) + (s0 >> 1) + sp;
        g_VTh[dst] = h;
        g_VTl[dst] = l;
    }
}

// ---------------------------------------------------------------------------
// Causal flash attention with bf16x3 mma.  64q x 64k tiles, 128 threads.
// Warp w owns 16 q rows. Softmax in fragments; P re-split and fed back as
// the A operand of PV (C-fragment layout == A-fragment layout).
// ---------------------------------------------------------------------------
__global__ __launch_bounds__(128)
void flash_mma_kernel()
{
    __shared__ uint32_t sKh[64][36], sKl[64][36];
    __shared__ uint32_t sVh[64][36], sVl[64][36];

    const int tid  = threadIdx.x;
    const int lane = tid & 31;
    const int warp = tid >> 5;
    const int g    = lane >> 2;
    const int t    = lane & 3;
    const int qb   = gridDim.x - 1 - blockIdx.x;
    const int bh   = blockIdx.y;
    const int q0   = qb * 64 + warp * 16;

    // Q fragments (A, m16k16): 4 dh-steps
    uint32_t qh[4][4], ql[4][4];
    {
        const uint32_t* qp = g_Qph + ((size_t)bh * S_ + q0) * 32;
        const uint32_t* qq = g_Qpl + ((size_t)bh * S_ + q0) * 32;
#pragma unroll
        for (int d = 0; d < 4; d++) {
            const int c0 = 8 * d + t;
            qh[d][0] = qp[g * 32 + c0];        qh[d][1] = qp[(g + 8) * 32 + c0];
            qh[d][2] = qp[g * 32 + c0 + 4];    qh[d][3] = qp[(g + 8) * 32 + c0 + 4];
            ql[d][0] = qq[g * 32 + c0];        ql[d][1] = qq[(g + 8) * 32 + c0];
            ql[d][2] = qq[g * 32 + c0 + 4];    ql[d][3] = qq[(g + 8) * 32 + c0 + 4];
        }
    }

    float oc[8][4];
#pragma unroll
    for (int nj = 0; nj < 8; nj++)
#pragma unroll
        for (int k = 0; k < 4; k++) oc[nj][k] = 0.f;
    float m0 = -1e30f, m1 = -1e30f, l0 = 0.f, l1 = 0.f;

    for (int kb = 0; kb <= qb; kb++) {
        __syncthreads();
        {
            const uint32_t* kh = g_Kph + ((size_t)bh * S_ + kb * 64) * 32;
            const uint32_t* kl = g_Kpl + ((size_t)bh * S_ + kb * 64) * 32;
            const uint32_t* vh = g_VTh + (size_t)bh * DH_ * (S_ / 2) + kb * 32;
            const uint32_t* vl = g_VTl + (size_t)bh * DH_ * (S_ / 2) + kb * 32;
#pragma unroll
            for (int i = 0; i < 4; i++) {
                const int v = tid + i * 128;   // 0..511 uint4
                const int r = v >> 3;          // row 0..63
                const int j = (v & 7) * 4;     // col 0..28
                *reinterpret_cast<uint4*>(&sKh[r][j]) =
                    *reinterpret_cast<const uint4*>(kh + r * 32 + j);
                *reinterpret_cast<uint4*>(&sKl[r][j]) =
                    *reinterpret_cast<const uint4*>(kl + r * 32 + j);
                *reinterpret_cast<uint4*>(&sVh[r][j]) =
                    *reinterpret_cast<const uint4*>(vh + r * (S_ / 2) + j);
                *reinterpret_cast<uint4*>(&sVl[r][j]) =
                    *reinterpret_cast<const uint4*>(vl + r * (S_ / 2) + j);
            }
        }
        __syncthreads();

        // ---- S = Q K^T ----
        float sc[8][4];
#pragma unroll
        for (int nj = 0; nj < 8; nj++)
#pragma unroll
            for (int k = 0; k < 4; k++) sc[nj][k] = 0.f;

#pragma unroll
        for (int d = 0; d < 4; d++) {
#pragma unroll
            for (int nj = 0; nj < 8; nj++) {
                const int rr = nj * 8 + g, cc = 8 * d + t;
                const uint32_t bh0 = sKh[rr][cc], bh1 = sKh[rr][cc + 4];
                const uint32_t bl0 = sKl[rr][cc], bl1 = sKl[rr][cc + 4];
                mma_bf16(sc[nj], qh[d][0], qh[d][1], qh[d][2], qh[d][3], bh0, bh1);
                mma_bf16(sc[nj], qh[d][0], qh[d][1], qh[d][2], qh[d][3], bl0, bl1);
                mma_bf16(sc[nj], ql[d][0], ql[d][1], ql[d][2], ql[d][3], bh0, bh1);
            }
        }

        if (kb == qb) {
            const int r0 = warp * 16 + g, r1 = r0 + 8;
#pragma unroll
            for (int nj = 0; nj < 8; nj++) {
                const int col = nj * 8 + 2 * t;
                if (col > r0)     sc[nj][0] = -1e30f;
                if (col + 1 > r0) sc[nj][1] = -1e30f;
                if (col > r1)     sc[nj][2] = -1e30f;
                if (col + 1 > r1) sc[nj][3] = -1e30f;
            }
        }

        // ---- softmax ----
        float rm0 = -1e30f, rm1 = -1e30f;
#pragma unroll
        for (int nj = 0; nj < 8; nj++) {
            rm0 = fmaxf(rm0, fmaxf(sc[nj][0], sc[nj][1]));
            rm1 = fmaxf(rm1, fmaxf(sc[nj][2], sc[nj][3]));
        }
        rm0 = fmaxf(rm0, __shfl_xor_sync(0xffffffffu, rm0, 1));
        rm0 = fmaxf(rm0, __shfl_xor_sync(0xffffffffu, rm0, 2));
        rm1 = fmaxf(rm1, __shfl_xor_sync(0xffffffffu, rm1, 1));
        rm1 = fmaxf(rm1, __shfl_xor_sync(0xffffffffu, rm1, 2));

        const float nm0 = fmaxf(m0, rm0), nm1 = fmaxf(m1, rm1);
        const float corr0 = __expf(m0 - nm0), corr1 = __expf(m1 - nm1);
        m0 = nm0; m1 = nm1;

        float rs0 = 0.f, rs1 = 0.f;
#pragma unroll
        for (int nj = 0; nj < 8; nj++) {
            sc[nj][0] = __expf(sc[nj][0] - m0);
            sc[nj][1] = __expf(sc[nj][1] - m0);
            sc[nj][2] = __expf(sc[nj][2] - m1);
            sc[nj][3] = __expf(sc[nj][3] - m1);
            rs0 += sc[nj][0] + sc[nj][1];
            rs1 += sc[nj][2] + sc[nj][3];
        }
        rs0 += __shfl_xor_sync(0xffffffffu, rs0, 1);
        rs0 += __shfl_xor_sync(0xffffffffu, rs0, 2);
        rs1 += __shfl_xor_sync(0xffffffffu, rs1, 1);
        rs1 += __shfl_xor_sync(0xffffffffu, rs1, 2);
        l0 = l0 * corr0 + rs0;
        l1 = l1 * corr1 + rs1;

#pragma unroll
        for (int nj = 0; nj < 8; nj++) {
            oc[nj][0] *= corr0; oc[nj][1] *= corr0;
            oc[nj][2] *= corr1; oc[nj][3] *= corr1;
        }

        // ---- O += P V ----
#pragma unroll
        for (int s = 0; s < 4; s++) {
            uint32_t ph[4], pl[4];
            split2(sc[2 * s][0],     sc[2 * s][1],     ph[0], pl[0]);
            split2(sc[2 * s][2],     sc[2 * s][3],     ph[1], pl[1]);
            split2(sc[2 * s + 1][0], sc[2 * s + 1][1], ph[2], pl[2]);
            split2(sc[2 * s + 1][2], sc[2 * s + 1][3], ph[3], pl[3]);
#pragma unroll
            for (int nj = 0; nj < 8; nj++) {
                const int rr = nj * 8 + g, cc = 8 * s + t;
                const uint32_t bh0 = sVh[rr][cc], bh1 = sVh[rr][cc + 4];
                const uint32_t bl0 = sVl[rr][cc], bl1 = sVl[rr][cc + 4];
                mma_bf16(oc[nj], ph[0], ph[1], ph[2], ph[3], bh0, bh1);
                mma_bf16(oc[nj], ph[0], ph[1], ph[2], ph[3], bl0, bl1);
                mma_bf16(oc[nj], pl[0], pl[1], pl[2], pl[3], bh0, bh1);
            }
        }
    }

    // epilogue
    const float inv0 = 1.f / l0, inv1 = 1.f / l1;
    const int b = bh >> 4, h = bh & 15;
    const int r0 = q0 + g, r1 = r0 + 8;
#pragma unroll
    for (int nj = 0; nj < 8; nj++) {
        const int col = h * 64 + nj * 8 + 2 * t;
        *reinterpret_cast<float2*>(g_attn + (size_t)(b * S_ + r0) * D_ + col) =
            make_float2(oc[nj][0] * inv0, oc[nj][1] * inv0);
        *reinterpret_cast<float2*>(g_attn + (size_t)(b * S_ + r1) * D_ + col) =
            make_float2(oc[nj][2] * inv1, oc[nj][3] * inv1);
    }
}

// ---------------------------------------------------------------------------
extern "C" void kernel_launch(void* const* d_in, const int* in_sizes, int n_in,
                              void* d_out, int out_size)
{
    const float* X    = (const float*)d_in[0];
    const float* Wqkv = (const float*)d_in[1];
    const float* Wo   = (const float*)d_in[2];
    float* out = (float*)d_out;
    (void)in_sizes; (void)n_in; (void)out_size;

    float *qkvp = nullptr, *attnp = nullptr;
    cudaGetSymbolAddress((void**)&qkvp, g_qkv);
    cudaGetSymbolAddress((void**)&attnp, g_attn);
    uint32_t *xhi, *xlo, *w1hi, *w1lo, *w2hi, *w2lo, *athi, *atlo;
    cudaGetSymbolAddress((void**)&xhi,  g_Xhi);
    cudaGetSymbolAddress((void**)&xlo,  g_Xlo);
    cudaGetSymbolAddress((void**)&w1hi, g_W1hi);
    cudaGetSymbolAddress((void**)&w1lo, g_W1lo);
    cudaGetSymbolAddress((void**)&w2hi, g_W2hi);
    cudaGetSymbolAddress((void**)&w2lo, g_W2lo);
    cudaGetSymbolAddress((void**)&athi, g_AThi);
    cudaGetSymbolAddress((void**)&atlo, g_ATlo);

    // 0) Split inputs into bf16 hi/lo
    {
        int n4 = M_ * D_ / 4;
        convert_kernel<<<n4 / 256, 256>>>(X, xhi, xlo, n4);
        n4 = 3 * D_ * D_ / 4;
        convert_kernel<<<n4 / 256, 256>>>(Wqkv, w1hi, w1lo, n4);
        n4 = D_ * D_ / 4;
        convert_kernel<<<n4 / 256, 256>>>(Wo, w2hi, w2lo, n4);
    }
    // 1) QKV projection
    {
        dim3 grid(3 * D_ / 128, M_ / 128);
        gemm_mma_kernel<<<grid, 256>>>(xhi, xlo, w1hi, w1lo, qkvp, M_, 3 * D_, D_ / 2);
    }
    // 2) RoPE + split (packed Q/K) + fp32 V
    {
        int total = BH_ * S_ * 32;
        rope_split_kernel<<<total / 256, 256>>>();
    }
    // 2b) V transpose + split
    {
        dim3 grid(S_ / 64, BH_);
        vtrans_kernel<<<grid, 256>>>();
    }
    // 3) Causal flash attention (bf16x3 mma)
    {
        dim3 grid(S_ / 64, BH_);
        flash_mma_kernel<<<grid, 128>>>();
    }
    // 4) Output projection
    {
        int n4 = M_ * D_ / 4;
        convert_kernel<<<n4 / 256, 256>>>(attnp, athi, atlo, n4);
        dim3 grid(D_ / 128, M_ / 128);
        gemm_mma_kernel<<<grid, 256>>>(athi, atlo, w2hi, w2lo, out, M_, D_, D_ / 2);
    }
}

// round 6
// speedup vs baseline: 2.5065x; 1.0438x over previous
#include <cuda_runtime.h>
#include <cuda_bf16.h>
#include <math.h>
#include <float.h>
#include <stdint.h>

namespace {
constexpr int B_  = 2;
constexpr int S_  = 2048;
constexpr int D_  = 1024;
constexpr int H_  = 16;
constexpr int DH_ = 64;
constexpr int M_  = B_ * S_;          // 4096
constexpr int BH_ = B_ * H_;          // 32
}

// Scratch (device globals — allocation is forbidden)
__device__ float g_qkv[(size_t)M_ * 3 * D_];           // [B,S,3,H,DH]
__device__ float g_v[(size_t)BH_ * S_ * DH_];          // [bh][s][dh] fp32
__device__ float g_attn[(size_t)M_ * D_];              // [B,S,D]

// Packed bf16x2 hi/lo operands
__device__ uint32_t g_Xhi[(size_t)M_ * D_ / 2],  g_Xlo[(size_t)M_ * D_ / 2];
__device__ uint32_t g_W1hi[(size_t)3 * D_ * D_ / 2], g_W1lo[(size_t)3 * D_ * D_ / 2];
__device__ uint32_t g_W2hi[(size_t)D_ * D_ / 2], g_W2lo[(size_t)D_ * D_ / 2];
__device__ uint32_t g_AThi[(size_t)M_ * D_ / 2], g_ATlo[(size_t)M_ * D_ / 2];
__device__ uint32_t g_Qph[(size_t)BH_ * S_ * 32], g_Qpl[(size_t)BH_ * S_ * 32];
__device__ uint32_t g_Kph[(size_t)BH_ * S_ * 32], g_Kpl[(size_t)BH_ * S_ * 32];
__device__ uint32_t g_VTh[(size_t)BH_ * DH_ * (S_ / 2)], g_VTl[(size_t)BH_ * DH_ * (S_ / 2)];

// ---------------------------------------------------------------------------
// helpers
// ---------------------------------------------------------------------------
__device__ __forceinline__ uint32_t smem_u32(const void* p) {
    uint32_t a;
    asm("{ .reg .u64 t; cvta.to.shared.u64 t, %1; cvt.u32.u64 %0, t; }"
        : "=r"(a) : "l"(p));
    return a;
}
__device__ __forceinline__ void split2(float a, float b, uint32_t& h, uint32_t& l)
{
    __nv_bfloat16 ha = __float2bfloat16(a), hb = __float2bfloat16(b);
    float ra = a - __bfloat162float(ha);
    float rb = b - __bfloat162float(hb);
    __nv_bfloat16 la = __float2bfloat16(ra), lb = __float2bfloat16(rb);
    h = ((uint32_t)__bfloat16_as_ushort(hb) << 16) | (uint32_t)__bfloat16_as_ushort(ha);
    l = ((uint32_t)__bfloat16_as_ushort(lb) << 16) | (uint32_t)__bfloat16_as_ushort(la);
}

__global__ void convert_kernel(const float* __restrict__ src,
                               uint32_t* __restrict__ hi,
                               uint32_t* __restrict__ lo, int n4)
{
    int i = blockIdx.x * blockDim.x + threadIdx.x;
    if (i >= n4) return;
    float4 x = reinterpret_cast<const float4*>(src)[i];
    uint2 h, l;
    split2(x.x, x.y, h.x, l.x);
    split2(x.z, x.w, h.y, l.y);
    reinterpret_cast<uint2*>(hi)[i] = h;
    reinterpret_cast<uint2*>(lo)[i] = l;
}

__device__ __forceinline__ void mma_bf16(float c[4],
                                         const uint32_t a[4],
                                         uint32_t b0, uint32_t b1)
{
    asm volatile(
        "mma.sync.aligned.m16n8k16.row.col.f32.bf16.bf16.f32 "
        "{%0,%1,%2,%3}, {%4,%5,%6,%7}, {%8,%9}, {%0,%1,%2,%3};"
        : "+f"(c[0]), "+f"(c[1]), "+f"(c[2]), "+f"(c[3])
        : "r"(a[0]), "r"(a[1]), "r"(a[2]), "r"(a[3]), "r"(b0), "r"(b1));
}
__device__ __forceinline__ void ldsm_x4(uint32_t& r0, uint32_t& r1,
                                        uint32_t& r2, uint32_t& r3, uint32_t addr)
{
    asm volatile("ldmatrix.sync.aligned.m8n8.x4.shared.b16 {%0,%1,%2,%3}, [%4];"
                 : "=r"(r0), "=r"(r1), "=r"(r2), "=r"(r3) : "r"(addr));
}
#define CP16(sa, gp) \
    asm volatile("cp.async.cg.shared.global [%0], [%1], 16;" :: "r"(sa), "l"(gp))
#define CP_COMMIT() asm volatile("cp.async.commit_group;" ::: "memory")

// ---------------------------------------------------------------------------
// GEMM-NT, bf16x3 mma, 2-stage cp.async pipeline + ldmatrix fragments.
// 128x128 CTA tile, 8 warps (4m x 2n), chunk = 16 pairs (32 bf16 of K).
// Dynamic smem: 2 stages x 4 buffers x 128 rows x 20 u32 = 81920 B.
// ---------------------------------------------------------------------------
__global__ __launch_bounds__(256, 2)
void gemm_mma_kernel(const uint32_t* __restrict__ Ahi, const uint32_t* __restrict__ Alo,
                     const uint32_t* __restrict__ Bhi, const uint32_t* __restrict__ Blo,
                     float* __restrict__ C, int M, int N, int K2)
{
    constexpr int PAD = 20;                 // u32 per row
    constexpr int BUF = 128 * PAD * 4;      // 10240 B per buffer
    constexpr int STG = 4 * BUF;            // 40960 B per stage
    extern __shared__ uint32_t dsm[];
    const uint32_t sbase = smem_u32(dsm);

    const int tid  = threadIdx.x;
    const int lane = tid & 31;
    const int wid  = tid >> 5;
    const int wm   = wid & 3;
    const int wn   = wid >> 2;
    const int bm   = blockIdx.y * 128;
    const int bn   = blockIdx.x * 128;

    // cp.async per-thread coords: rows (tid>>2) and +64, word group (tid&3)*4
    const int cr = tid >> 2;
    const int cj = (tid & 3) << 2;
    // ldmatrix per-lane coords
    const int arow = lane & 15;
    const int asel = ((lane >> 4) << 2);
    const int brow = (lane & 7) + ((lane >> 4) << 3);
    const int bsel = (((lane >> 3) & 1) << 2);

    float c[2][8][4];
#pragma unroll
    for (int mi = 0; mi < 2; mi++)
#pragma unroll
        for (int nj = 0; nj < 8; nj++)
#pragma unroll
            for (int k = 0; k < 4; k++) c[mi][nj][k] = 0.f;

    auto issue = [&](int cc, int stage) {
        const int kp = cc << 4;
        const uint32_t so = sbase + stage * STG;
        const size_t ga0 = (size_t)(bm + cr) * K2 + kp + cj;
        const size_t ga1 = (size_t)(bm + cr + 64) * K2 + kp + cj;
        const size_t gb0 = (size_t)(bn + cr) * K2 + kp + cj;
        const size_t gb1 = (size_t)(bn + cr + 64) * K2 + kp + cj;
        const uint32_t d0 = (uint32_t)(cr * PAD + cj) * 4;
        const uint32_t d1 = (uint32_t)((cr + 64) * PAD + cj) * 4;
        CP16(so + d0,           Ahi + ga0);  CP16(so + d1,           Ahi + ga1);
        CP16(so + BUF + d0,     Alo + ga0);  CP16(so + BUF + d1,     Alo + ga1);
        CP16(so + 2 * BUF + d0, Bhi + gb0);  CP16(so + 2 * BUF + d1, Bhi + gb1);
        CP16(so + 3 * BUF + d0, Blo + gb0);  CP16(so + 3 * BUF + d1, Blo + gb1);
        CP_COMMIT();
    };

    auto compute = [&](int stage) {
        const uint32_t so = sbase + stage * STG;
#pragma unroll
        for (int step = 0; step < 2; step++) {
            const int ko = step << 3;
            uint32_t aH[2][4], aL[2][4];
#pragma unroll
            for (int mi = 0; mi < 2; mi++) {
                const uint32_t ra = so +
                    (uint32_t)((wm * 32 + mi * 16 + arow) * PAD + ko + asel) * 4;
                ldsm_x4(aH[mi][0], aH[mi][1], aH[mi][2], aH[mi][3], ra);
                ldsm_x4(aL[mi][0], aL[mi][1], aL[mi][2], aL[mi][3], ra + BUF);
            }
#pragma unroll
            for (int nj2 = 0; nj2 < 4; nj2++) {
                const uint32_t rb = so + 2 * BUF +
                    (uint32_t)((wn * 64 + nj2 * 16 + brow) * PAD + ko + bsel) * 4;
                uint32_t bh[4], bl[4];
                ldsm_x4(bh[0], bh[1], bh[2], bh[3], rb);
                ldsm_x4(bl[0], bl[1], bl[2], bl[3], rb + BUF);
#pragma unroll
                for (int mi = 0; mi < 2; mi++) {
                    mma_bf16(c[mi][2 * nj2],     aH[mi], bh[0], bh[1]);
                    mma_bf16(c[mi][2 * nj2],     aH[mi], bl[0], bl[1]);
                    mma_bf16(c[mi][2 * nj2],     aL[mi], bh[0], bh[1]);
                    mma_bf16(c[mi][2 * nj2 + 1], aH[mi], bh[2], bh[3]);
                    mma_bf16(c[mi][2 * nj2 + 1], aH[mi], bl[2], bl[3]);
                    mma_bf16(c[mi][2 * nj2 + 1], aL[mi], bh[2], bh[3]);
                }
            }
        }
    };

    const int nchunks = K2 >> 4;
    issue(0, 0);
    for (int cc = 0; cc < nchunks; cc++) {
        if (cc + 1 < nchunks) {
            issue(cc + 1, (cc + 1) & 1);
            asm volatile("cp.async.wait_group 1;" ::: "memory");
        } else {
            asm volatile("cp.async.wait_group 0;" ::: "memory");
        }
        __syncthreads();
        compute(cc & 1);
        __syncthreads();
    }

    const int g = lane >> 2, t = lane & 3;
#pragma unroll
    for (int mi = 0; mi < 2; mi++) {
        const int row = bm + wm * 32 + mi * 16 + g;
#pragma unroll
        for (int nj = 0; nj < 8; nj++) {
            const int col = bn + wn * 64 + nj * 8 + 2 * t;
            *reinterpret_cast<float2*>(C + (size_t)row * N + col) =
                make_float2(c[mi][nj][0], c[mi][nj][1]);
            *reinterpret_cast<float2*>(C + (size_t)(row + 8) * N + col) =
                make_float2(c[mi][nj][2], c[mi][nj][3]);
        }
    }
}

// ---------------------------------------------------------------------------
// RoPE + split. Packed bf16 hi/lo Q (pre-scaled) and K, fp32 V.
// ---------------------------------------------------------------------------
__global__ void rope_split_kernel()
{
    int idx = blockIdx.x * blockDim.x + threadIdx.x;
    if (idx >= BH_ * S_ * 32) return;
    const int p = idx & 31;
    int t = idx >> 5;
    const int s = t & (S_ - 1);
    t >>= 11;
    const int h = t & (H_ - 1);
    const int b = t >> 4;
    const int bh = b * H_ + h;

    const size_t row = (size_t)(b * S_ + s) * (3 * D_) + h * DH_;
    const float qe = g_qkv[row + 2 * p],          qo = g_qkv[row + 2 * p + 1];
    const float ke = g_qkv[row + D_ + 2 * p],     ko = g_qkv[row + D_ + 2 * p + 1];
    const float ve = g_qkv[row + 2 * D_ + 2 * p], vo = g_qkv[row + 2 * D_ + 2 * p + 1];

    const double invf = exp(-9.210340371976184 * (double)(2 * p) / 64.0);
    const double ang  = (double)s * invf;
    double sd, cd;
    sincos(ang, &sd, &cd);
    const float c = (float)cd, sn = (float)sd;

    const size_t po = ((size_t)bh * S_ + s) * 32 + p;
    uint32_t h32, l32;
    split2(0.125f * (qe * c - qo * sn), 0.125f * (qe * sn + qo * c), h32, l32);
    g_Qph[po] = h32; g_Qpl[po] = l32;
    split2(ke * c - ko * sn, ke * sn + ko * c, h32, l32);
    g_Kph[po] = h32; g_Kpl[po] = l32;

    const size_t vo_ = ((size_t)bh * S_ + s) * DH_ + 2 * p;
    g_v[vo_]     = ve;
    g_v[vo_ + 1] = vo;
}

// ---------------------------------------------------------------------------
// V transpose + bf16 split: g_v [bh][s][d] -> VT [bh][d][spair] packed.
// ---------------------------------------------------------------------------
__global__ __launch_bounds__(256)
void vtrans_kernel()
{
    __shared__ float sv[64][65];
    const int tid = threadIdx.x;
    const int bh  = blockIdx.y;
    const int s0  = blockIdx.x * 64;

    const float* vg = g_v + ((size_t)bh * S_ + s0) * DH_;
#pragma unroll
    for (int i = 0; i < 4; i++) {
        int idx = tid + i * 256;
        int r = idx >> 4, c = (idx & 15) * 4;
        float4 v = *reinterpret_cast<const float4*>(vg + r * DH_ + c);
        sv[r][c] = v.x; sv[r][c + 1] = v.y; sv[r][c + 2] = v.z; sv[r][c + 3] = v.w;
    }
    __syncthreads();
#pragma unroll
    for (int i = 0; i < 8; i++) {
        int o = tid + i * 256;
        int d = o >> 5, sp = o & 31;
        uint32_t h, l;
        split2(sv[2 * sp][d], sv[2 * sp + 1][d], h, l);
        size_t dst = ((size_t)bh * DH_ + d) * (S_ / 2) + (s0 >> 1) + sp;
        g_VTh[dst] = h;
        g_VTl[dst] = l;
    }
}

// ---------------------------------------------------------------------------
// Causal flash attention, bf16x3 mma + ldmatrix + cp.async staging.
// ---------------------------------------------------------------------------
__global__ __launch_bounds__(128)
void flash_mma_kernel()
{
    __shared__ uint32_t sKh[64][36], sKl[64][36];
    __shared__ uint32_t sVh[64][36], sVl[64][36];

    const int tid  = threadIdx.x;
    const int lane = tid & 31;
    const int warp = tid >> 5;
    const int g    = lane >> 2;
    const int t    = lane & 3;
    const int qb   = gridDim.x - 1 - blockIdx.x;
    const int bh   = blockIdx.y;
    const int q0   = qb * 64 + warp * 16;

    const uint32_t sKh_b = smem_u32(sKh), sKl_b = smem_u32(sKl);
    const uint32_t sVh_b = smem_u32(sVh), sVl_b = smem_u32(sVl);
    const int brow = (lane & 7) + ((lane >> 4) << 3);
    const int bsel = (((lane >> 3) & 1) << 2);

    // Q fragments (A, m16k16): 4 dh-steps
    uint32_t qh[4][4], ql[4][4];
    {
        const uint32_t* qp = g_Qph + ((size_t)bh * S_ + q0) * 32;
        const uint32_t* qq = g_Qpl + ((size_t)bh * S_ + q0) * 32;
#pragma unroll
        for (int d = 0; d < 4; d++) {
            const int c0 = 8 * d + t;
            qh[d][0] = qp[g * 32 + c0];        qh[d][1] = qp[(g + 8) * 32 + c0];
            qh[d][2] = qp[g * 32 + c0 + 4];    qh[d][3] = qp[(g + 8) * 32 + c0 + 4];
            ql[d][0] = qq[g * 32 + c0];        ql[d][1] = qq[(g + 8) * 32 + c0];
            ql[d][2] = qq[g * 32 + c0 + 4];    ql[d][3] = qq[(g + 8) * 32 + c0 + 4];
        }
    }

    float oc[8][4];
#pragma unroll
    for (int nj = 0; nj < 8; nj++)
#pragma unroll
        for (int k = 0; k < 4; k++) oc[nj][k] = 0.f;
    float m0 = -1e30f, m1 = -1e30f, l0 = 0.f, l1 = 0.f;

    for (int kb = 0; kb <= qb; kb++) {
        __syncthreads();
        {
            const uint32_t* kh = g_Kph + ((size_t)bh * S_ + kb * 64) * 32;
            const uint32_t* kl = g_Kpl + ((size_t)bh * S_ + kb * 64) * 32;
            const uint32_t* vh = g_VTh + (size_t)bh * DH_ * (S_ / 2) + kb * 32;
            const uint32_t* vl = g_VTl + (size_t)bh * DH_ * (S_ / 2) + kb * 32;
#pragma unroll
            for (int i = 0; i < 4; i++) {
                const int v = tid + i * 128;   // 0..511
                const int r = v >> 3;          // row 0..63
                const int j = (v & 7) * 4;     // word 0..28
                const uint32_t dd = (uint32_t)(r * 36 + j) * 4;
                CP16(sKh_b + dd, kh + r * 32 + j);
                CP16(sKl_b + dd, kl + r * 32 + j);
                CP16(sVh_b + dd, vh + r * (S_ / 2) + j);
                CP16(sVl_b + dd, vl + r * (S_ / 2) + j);
            }
            CP_COMMIT();
            asm volatile("cp.async.wait_group 0;" ::: "memory");
        }
        __syncthreads();

        // ---- S = Q K^T ----
        float sc[8][4];
#pragma unroll
        for (int nj = 0; nj < 8; nj++)
#pragma unroll
            for (int k = 0; k < 4; k++) sc[nj][k] = 0.f;

#pragma unroll
        for (int d = 0; d < 4; d++) {
#pragma unroll
            for (int nj2 = 0; nj2 < 4; nj2++) {
                const uint32_t off =
                    (uint32_t)((nj2 * 16 + brow) * 36 + 8 * d + bsel) * 4;
                uint32_t kh4[4], kl4[4];
                ldsm_x4(kh4[0], kh4[1], kh4[2], kh4[3], sKh_b + off);
                ldsm_x4(kl4[0], kl4[1], kl4[2], kl4[3], sKl_b + off);
                mma_bf16(sc[2 * nj2],     qh[d], kh4[0], kh4[1]);
                mma_bf16(sc[2 * nj2],     qh[d], kl4[0], kl4[1]);
                mma_bf16(sc[2 * nj2],     ql[d], kh4[0], kh4[1]);
                mma_bf16(sc[2 * nj2 + 1], qh[d], kh4[2], kh4[3]);
                mma_bf16(sc[2 * nj2 + 1], qh[d], kl4[2], kl4[3]);
                mma_bf16(sc[2 * nj2 + 1], ql[d], kh4[2], kh4[3]);
            }
        }

        if (kb == qb) {
            const int r0 = warp * 16 + g, r1 = r0 + 8;
#pragma unroll
            for (int nj = 0; nj < 8; nj++) {
                const int col = nj * 8 + 2 * t;
                if (col > r0)     sc[nj][0] = -1e30f;
                if (col + 1 > r0) sc[nj][1] = -1e30f;
                if (col > r1)     sc[nj][2] = -1e30f;
                if (col + 1 > r1) sc[nj][3] = -1e30f;
            }
        }

        // ---- softmax ----
        float rm0 = -1e30f, rm1 = -1e30f;
#pragma unroll
        for (int nj = 0; nj < 8; nj++) {
            rm0 = fmaxf(rm0, fmaxf(sc[nj][0], sc[nj][1]));
            rm1 = fmaxf(rm1, fmaxf(sc[nj][2], sc[nj][3]));
        }
        rm0 = fmaxf(rm0, __shfl_xor_sync(0xffffffffu, rm0, 1));
        rm0 = fmaxf(rm0, __shfl_xor_sync(0xffffffffu, rm0, 2));
        rm1 = fmaxf(rm1, __shfl_xor_sync(0xffffffffu, rm1, 1));
        rm1 = fmaxf(rm1, __shfl_xor_sync(0xffffffffu, rm1, 2));

        const float nm0 = fmaxf(m0, rm0), nm1 = fmaxf(m1, rm1);
        const float corr0 = __expf(m0 - nm0), corr1 = __expf(m1 - nm1);
        m0 = nm0; m1 = nm1;

        float rs0 = 0.f, rs1 = 0.f;
#pragma unroll
        for (int nj = 0; nj < 8; nj++) {
            sc[nj][0] = __expf(sc[nj][0] - m0);
            sc[nj][1] = __expf(sc[nj][1] - m0);
            sc[nj][2] = __expf(sc[nj][2] - m1);
            sc[nj][3] = __expf(sc[nj][3] - m1);
            rs0 += sc[nj][0] + sc[nj][1];
            rs1 += sc[nj][2] + sc[nj][3];
        }
        rs0 += __shfl_xor_sync(0xffffffffu, rs0, 1);
        rs0 += __shfl_xor_sync(0xffffffffu, rs0, 2);
        rs1 += __shfl_xor_sync(0xffffffffu, rs1, 1);
        rs1 += __shfl_xor_sync(0xffffffffu, rs1, 2);
        l0 = l0 * corr0 + rs0;
        l1 = l1 * corr1 + rs1;

#pragma unroll
        for (int nj = 0; nj < 8; nj++) {
            oc[nj][0] *= corr0; oc[nj][1] *= corr0;
            oc[nj][2] *= corr1; oc[nj][3] *= corr1;
        }

        // ---- O += P V ----
#pragma unroll
        for (int s = 0; s < 4; s++) {
            uint32_t ph[4], pl[4];
            split2(sc[2 * s][0],     sc[2 * s][1],     ph[0], pl[0]);
            split2(sc[2 * s][2],     sc[2 * s][3],     ph[1], pl[1]);
            split2(sc[2 * s + 1][0], sc[2 * s + 1][1], ph[2], pl[2]);
            split2(sc[2 * s + 1][2], sc[2 * s + 1][3], ph[3], pl[3]);
#pragma unroll
            for (int nj2 = 0; nj2 < 4; nj2++) {
                const uint32_t off =
                    (uint32_t)((nj2 * 16 + brow) * 36 + 8 * s + bsel) * 4;
                uint32_t vh4[4], vl4[4];
                ldsm_x4(vh4[0], vh4[1], vh4[2], vh4[3], sVh_b + off);
                ldsm_x4(vl4[0], vl4[1], vl4[2], vl4[3], sVl_b + off);
                mma_bf16(oc[2 * nj2],     ph, vh4[0], vh4[1]);
                mma_bf16(oc[2 * nj2],     ph, vl4[0], vl4[1]);
                mma_bf16(oc[2 * nj2],     pl, vh4[0], vh4[1]);
                mma_bf16(oc[2 * nj2 + 1], ph, vh4[2], vh4[3]);
                mma_bf16(oc[2 * nj2 + 1], ph, vl4[2], vl4[3]);
                mma_bf16(oc[2 * nj2 + 1], pl, vh4[2], vh4[3]);
            }
        }
    }

    // epilogue
    const float inv0 = 1.f / l0, inv1 = 1.f / l1;
    const int b = bh >> 4, h = bh & 15;
    const int r0 = q0 + g, r1 = r0 + 8;
#pragma unroll
    for (int nj = 0; nj < 8; nj++) {
        const int col = h * 64 + nj * 8 + 2 * t;
        *reinterpret_cast<float2*>(g_attn + (size_t)(b * S_ + r0) * D_ + col) =
            make_float2(oc[nj][0] * inv0, oc[nj][1] * inv0);
        *reinterpret_cast<float2*>(g_attn + (size_t)(b * S_ + r1) * D_ + col) =
            make_float2(oc[nj][2] * inv1, oc[nj][3] * inv1);
    }
}

// ---------------------------------------------------------------------------
extern "C" void kernel_launch(void* const* d_in, const int* in_sizes, int n_in,
                              void* d_out, int out_size)
{
    const float* X    = (const float*)d_in[0];
    const float* Wqkv = (const float*)d_in[1];
    const float* Wo   = (const float*)d_in[2];
    float* out = (float*)d_out;
    (void)in_sizes; (void)n_in; (void)out_size;

    float *qkvp = nullptr, *attnp = nullptr;
    cudaGetSymbolAddress((void**)&qkvp, g_qkv);
    cudaGetSymbolAddress((void**)&attnp, g_attn);
    uint32_t *xhi, *xlo, *w1hi, *w1lo, *w2hi, *w2lo, *athi, *atlo;
    cudaGetSymbolAddress((void**)&xhi,  g_Xhi);
    cudaGetSymbolAddress((void**)&xlo,  g_Xlo);
    cudaGetSymbolAddress((void**)&w1hi, g_W1hi);
    cudaGetSymbolAddress((void**)&w1lo, g_W1lo);
    cudaGetSymbolAddress((void**)&w2hi, g_W2hi);
    cudaGetSymbolAddress((void**)&w2lo, g_W2lo);
    cudaGetSymbolAddress((void**)&athi, g_AThi);
    cudaGetSymbolAddress((void**)&atlo, g_ATlo);

    const int gemm_smem = 2 * 4 * 128 * 20 * 4;   // 81920 B
    cudaFuncSetAttribute(gemm_mma_kernel,
                         cudaFuncAttributeMaxDynamicSharedMemorySize, gemm_smem);

    // 0) Split inputs into bf16 hi/lo
    {
        int n4 = M_ * D_ / 4;
        convert_kernel<<<n4 / 256, 256>>>(X, xhi, xlo, n4);
        n4 = 3 * D_ * D_ / 4;
        convert_kernel<<<n4 / 256, 256>>>(Wqkv, w1hi, w1lo, n4);
        n4 = D_ * D_ / 4;
        convert_kernel<<<n4 / 256, 256>>>(Wo, w2hi, w2lo, n4);
    }
    // 1) QKV projection
    {
        dim3 grid(3 * D_ / 128, M_ / 128);
        gemm_mma_kernel<<<grid, 256, gemm_smem>>>(xhi, xlo, w1hi, w1lo, qkvp,
                                                  M_, 3 * D_, D_ / 2);
    }
    // 2) RoPE + split (packed Q/K) + fp32 V
    {
        int total = BH_ * S_ * 32;
        rope_split_kernel<<<total / 256, 256>>>();
    }
    // 2b) V transpose + split
    {
        dim3 grid(S_ / 64, BH_);
        vtrans_kernel<<<grid, 256>>>();
    }
    // 3) Causal flash attention
    {
        dim3 grid(S_ / 64, BH_);
        flash_mma_kernel<<<grid, 128>>>();
    }
    // 4) Output projection
    {
        int n4 = M_ * D_ / 4;
        convert_kernel<<<n4 / 256, 256>>>(attnp, athi, atlo, n4);
        dim3 grid(D_ / 128, M_ / 128);
        gemm_mma_kernel<<<grid, 256, gemm_smem>>>(athi, atlo, w2hi, w2lo, out,
                                                  M_, D_, D_ / 2);
    }
}